// round 2
// baseline (speedup 1.0000x reference)
#include <cuda_runtime.h>
#include <cstddef>

// ---------------------------------------------------------------------------
// GRU recurrence, persistent-kernel fp32 baseline.
//
// Shapes: x (B=512, T=512, IN=128), W_ih (768,128), W_hh (768,256),
//         bias_g (768), bias_n (256), w_lin (128,256), bias_out (128)
// Output: h_final @ w_lin^T + bias_out  -> (512, 128) fp32
//
// Design:
//   * ONE persistent kernel, 128 blocks (<=148 SMs -> all co-resident),
//     grid-wide generation barrier once per timestep.
//   * Per block: batch tile of 64 rows x 16 hidden units (= 48 gate columns
//     r/z/n). Its 48x384 weight slice ([W_ih | W_hh], gate-permuted) lives in
//     padded SMEM for the whole run.
//   * Per step: stage x_t tile (64x128) + h tile (64x256) into padded SMEM,
//     fp32 FFMA GEMM with register tile 4 rows x {r,z,n}, fused GRU epilogue,
//     write h_new into the ping-pong global h buffer, grid barrier.
//   * n-gate x-part and h-part are accumulated separately (reference applies
//     r only to the h-part + bias_n).
//   * h is double buffered: step t reads g_h[t&1], writes g_h[(t+1)&1], so a
//     single barrier per step is sufficient (no RAW/WAR hazard).
//   * All g_h reads use __ldcg (L2) — L1 is not coherent across blocks and
//     the same addresses are re-read every other step.
// ---------------------------------------------------------------------------

#define BB      512
#define TT      512
#define IN_DIM  128
#define HH      256
#define OUT_DIM 128

#define NBLK 128     // 8 batch chunks x 16 hidden chunks
#define NTHR 256
#define MB   64      // batch rows per block
#define UHN  16      // hidden units per block
#define NC   48      // gate columns per block (r,z,n for 16 units)

// padded SMEM strides (floats): %32 != 0 for conflict-free LDS.128,
// *4 bytes % 16 == 0 for alignment
#define AXS 132      // x tile row stride   (64 x 132)
#define AHS 260      // h tile row stride   (64 x 260)
#define WTS 388      // W slice row stride  (48 x 388)

#define SMEM_FLOATS (MB*AXS + MB*AHS + NC*WTS)
#define SMEM_BYTES  (SMEM_FLOATS * 4)

__device__ unsigned g_count = 0;   // barrier arrival counter (returns to 0)
__device__ unsigned g_gen   = 0;   // barrier generation (monotonic, wrap-safe)
__device__ float    g_h[2][BB][HH];   // ping-pong hidden state (1 MB)

__device__ __forceinline__ float sigmoid_f(float v) {
    return 1.0f / (1.0f + __expf(-v));
}

extern "C" __global__ void __launch_bounds__(NTHR, 1)
gru_persistent_kernel(const float* __restrict__ x,
                      const float* __restrict__ wih,
                      const float* __restrict__ whh,
                      const float* __restrict__ bg,
                      const float* __restrict__ bn,
                      const float* __restrict__ wlin,
                      const float* __restrict__ bout,
                      float* __restrict__ out)
{
    extern __shared__ float sm[];
    float* Ax = sm;                  // [MB][AXS]  x_t tile
    float* Ah = Ax + MB * AXS;       // [MB][AHS]  h tile
    float* Wt = Ah + MB * AHS;       // [NC][WTS]  weight slice (persists)

    const int tid = threadIdx.x;
    const int bid = blockIdx.x;
    const int bc  = bid >> 4;        // batch chunk 0..7
    const int gch = bid & 15;        // hidden chunk 0..15
    const int b0  = bc * MB;
    const int u0  = gch * UHN;

    const int tx = tid & 15;         // hidden unit within chunk
    const int ty = tid >> 4;         // row group (4 rows each)
    const int u  = u0 + tx;          // global hidden unit of this thread

    // Snapshot barrier generation before any block can possibly advance it.
    const unsigned base = *(volatile unsigned*)&g_gen;

    // Per-thread biases (constant across rows and steps).
    const float bgr = bg[u];
    const float bgz = bg[HH + u];
    const float bgn = bg[2 * HH + u];
    const float bnn = bn[u];

    // ---- Stage weight slice once: rows = [r(16); z(16); n(16)] of this
    //      hidden chunk, cols = [W_ih(128) | W_hh(256)] ----
    for (int i = tid; i < NC * 96; i += NTHR) {
        const int c = i / 96, q = i % 96;      // q indexes float4s along K
        const int gt  = c >> 4;                // 0=r, 1=z, 2=n
        const int row = gt * HH + u0 + (c & 15);
        float4 v;
        if (q < 32) v = __ldg((const float4*)(wih + (size_t)row * IN_DIM) + q);
        else        v = __ldg((const float4*)(whh + (size_t)row * HH) + (q - 32));
        *(float4*)(Wt + c * WTS + 4 * q) = v;
    }

    const float* wr = Wt + tx * WTS;
    const float* wz = Wt + (16 + tx) * WTS;
    const float* wn = Wt + (32 + tx) * WTS;

    // ================= time loop =================
    for (int t = 0; t < TT; ++t) {
        const int cur = t & 1;
        const int nxt = cur ^ 1;

        // ---- stage x_t tile (64 x 128) ----
        for (int i = tid; i < MB * 32; i += NTHR) {
            const int m = i >> 5, q = i & 31;
            float4 v = __ldg((const float4*)(x + ((size_t)(b0 + m) * TT + t) * IN_DIM) + q);
            *(float4*)(Ax + m * AXS + 4 * q) = v;
        }
        // ---- stage h tile (64 x 256); zeros at t==0 ----
        for (int i = tid; i < MB * 64; i += NTHR) {
            const int m = i >> 6, q = i & 63;
            float4 v;
            if (t > 0) v = __ldcg((const float4*)(&g_h[cur][b0 + m][0]) + q);
            else       { v.x = 0.f; v.y = 0.f; v.z = 0.f; v.w = 0.f; }
            *(float4*)(Ah + m * AHS + 4 * q) = v;
        }
        __syncthreads();

        float ar[4]  = {0.f, 0.f, 0.f, 0.f};
        float az[4]  = {0.f, 0.f, 0.f, 0.f};
        float anx[4] = {0.f, 0.f, 0.f, 0.f};   // n-gate, x part
        float anh[4] = {0.f, 0.f, 0.f, 0.f};   // n-gate, h part

        const float* a0  = Ax + (4 * ty) * AXS;
        const float* ah0 = Ah + (4 * ty) * AHS;

        // ---- K loop, x part (k = 0..127) ----
        #pragma unroll 2
        for (int k = 0; k < IN_DIM; k += 4) {
            const float4 br = *(const float4*)(wr + k);
            const float4 bz = *(const float4*)(wz + k);
            const float4 bv = *(const float4*)(wn + k);
            #pragma unroll
            for (int r = 0; r < 4; ++r) {
                const float4 a = *(const float4*)(a0 + r * AXS + k);
                ar[r]  = fmaf(a.x, br.x, ar[r]);  ar[r]  = fmaf(a.y, br.y, ar[r]);
                ar[r]  = fmaf(a.z, br.z, ar[r]);  ar[r]  = fmaf(a.w, br.w, ar[r]);
                az[r]  = fmaf(a.x, bz.x, az[r]);  az[r]  = fmaf(a.y, bz.y, az[r]);
                az[r]  = fmaf(a.z, bz.z, az[r]);  az[r]  = fmaf(a.w, bz.w, az[r]);
                anx[r] = fmaf(a.x, bv.x, anx[r]); anx[r] = fmaf(a.y, bv.y, anx[r]);
                anx[r] = fmaf(a.z, bv.z, anx[r]); anx[r] = fmaf(a.w, bv.w, anx[r]);
            }
        }
        // ---- K loop, h part (k = 0..255, weight offset +128) ----
        #pragma unroll 2
        for (int k = 0; k < HH; k += 4) {
            const float4 br = *(const float4*)(wr + IN_DIM + k);
            const float4 bz = *(const float4*)(wz + IN_DIM + k);
            const float4 bv = *(const float4*)(wn + IN_DIM + k);
            #pragma unroll
            for (int r = 0; r < 4; ++r) {
                const float4 a = *(const float4*)(ah0 + r * AHS + k);
                ar[r]  = fmaf(a.x, br.x, ar[r]);  ar[r]  = fmaf(a.y, br.y, ar[r]);
                ar[r]  = fmaf(a.z, br.z, ar[r]);  ar[r]  = fmaf(a.w, br.w, ar[r]);
                az[r]  = fmaf(a.x, bz.x, az[r]);  az[r]  = fmaf(a.y, bz.y, az[r]);
                az[r]  = fmaf(a.z, bz.z, az[r]);  az[r]  = fmaf(a.w, bz.w, az[r]);
                anh[r] = fmaf(a.x, bv.x, anh[r]); anh[r] = fmaf(a.y, bv.y, anh[r]);
                anh[r] = fmaf(a.z, bv.z, anh[r]); anh[r] = fmaf(a.w, bv.w, anh[r]);
            }
        }

        // ---- fused GRU epilogue ----
        #pragma unroll
        for (int r = 0; r < 4; ++r) {
            const int m = 4 * ty + r;
            const float rr   = sigmoid_f(ar[r] + bgr);
            const float zz   = sigmoid_f(az[r] + bgz);
            const float nn   = tanhf(anx[r] + bgn + rr * (anh[r] + bnn));
            const float hold = Ah[m * AHS + u];              // h_{t-1}[m][u]
            g_h[nxt][b0 + m][u] = nn + zz * (hold - nn);
        }

        // ---- grid-wide barrier (one per step) ----
        __syncthreads();                 // everyone done with SMEM + stores issued
        if (tid == 0) {
            __threadfence();             // publish h_new before arrival
            const unsigned old = atomicAdd(&g_count, 1);
            if (old == NBLK - 1) {
                atomicExch(&g_count, 0);
                __threadfence();
                atomicAdd(&g_gen, 1);
            } else {
                while (*(volatile unsigned*)&g_gen - base < (unsigned)(t + 1)) { }
            }
            __threadfence();             // acquire side
        }
        __syncthreads();
    }

    // ============ final projection: out = h_final @ w_lin^T + bias_out ============
    // h_final lives in g_h[0] (T is even). Block computes rows [b0,b0+64),
    // output cols [gch*8, gch*8+8).
    for (int i = tid; i < MB * 64; i += NTHR) {
        const int m = i >> 6, q = i & 63;
        float4 v = __ldcg((const float4*)(&g_h[0][b0 + m][0]) + q);
        *(float4*)(Ah + m * AHS + 4 * q) = v;
    }
    const int c0 = gch * 8;
    for (int i = tid; i < 8 * 64; i += NTHR) {
        const int c = i >> 6, q = i & 63;
        float4 v = __ldg((const float4*)(wlin + (size_t)(c0 + c) * HH) + q);
        *(float4*)(Wt + c * WTS + 4 * q) = v;
    }
    __syncthreads();

    #pragma unroll
    for (int p = 0; p < 2; ++p) {
        const int o = tid + p * NTHR;        // 0..511
        const int m = o >> 3;
        const int c = o & 7;
        const float* hv = Ah + m * AHS;
        const float* wv = Wt + c * WTS;
        float acc = 0.f;
        #pragma unroll 8
        for (int k = 0; k < HH; ++k) acc = fmaf(hv[k], wv[k], acc);
        out[(size_t)(b0 + m) * OUT_DIM + c0 + c] = acc + bout[c0 + c];
    }
}

// ---------------------------------------------------------------------------
extern "C" void kernel_launch(void* const* d_in, const int* in_sizes, int n_in,
                              void* d_out, int out_size)
{
    (void)in_sizes; (void)n_in; (void)out_size;
    const float* x    = (const float*)d_in[0];
    const float* wih  = (const float*)d_in[1];
    const float* whh  = (const float*)d_in[2];
    const float* bg   = (const float*)d_in[3];
    const float* bn   = (const float*)d_in[4];
    const float* wlin = (const float*)d_in[5];
    const float* bout = (const float*)d_in[6];
    float* out = (float*)d_out;

    // Idempotent, capture-safe (not a stream operation).
    cudaFuncSetAttribute(gru_persistent_kernel,
                         cudaFuncAttributeMaxDynamicSharedMemorySize, SMEM_BYTES);

    gru_persistent_kernel<<<NBLK, NTHR, SMEM_BYTES>>>(
        x, wih, whh, bg, bn, wlin, bout, out);
}